// round 8
// baseline (speedup 1.0000x reference)
#include <cuda_runtime.h>

// LearnedPosMapT: out[b,w,m,v,s] = sum_n table[m-n+7, s] * x[b,w,n,v,s] + bias[m]
// Shapes: x (8, 3136, 8, 384) f32, table (15, 8) f32, bias (1, 8, 1) f32.
// W = 8 (window), GAMMA = s = 8, v = 48, DIM = v*s = 384.
//
// Memory-bound: 308 MB in + 308 MB out. One thread per (window, d/4) float4
// column: 8 coalesced float4 loads, 64 FMA4, 8 coalesced float4 stores.

#define WINSZ 8
#define DIMSZ 384
#define VEC   (DIMSZ / 4)   // 96 float4 per row
#define ROWF4 VEC           // float4 stride between window rows

__global__ __launch_bounds__(256, 2)
void lpm_kernel(const float* __restrict__ x,
                const float* __restrict__ table,   // (15, 8)
                const float* __restrict__ bias,    // (8)
                float* __restrict__ out,
                int n_win)                          // B * NWIN
{
    const int t = blockIdx.x * blockDim.x + threadIdx.x;
    const int total = n_win * VEC;
    if (t >= total) return;

    const int win = t / VEC;
    const int c   = t - win * VEC;        // float4 column index within a row
    const int s0  = (c * 4) & 7;          // starting gamma index (0 or 4)

    const float4* __restrict__ xin =
        reinterpret_cast<const float4*>(x) + (size_t)win * (WINSZ * ROWF4) + c;
    float4* __restrict__ o =
        reinterpret_cast<float4*>(out) + (size_t)win * (WINSZ * ROWF4) + c;

    // Load the 15 relevant weight rows: table[k][s0..s0+3]. 16B aligned
    // (k*8 + s0 is a multiple of 4 floats). L1-resident broadcast.
    float4 wt[15];
#pragma unroll
    for (int k = 0; k < 15; k++)
        wt[k] = *reinterpret_cast<const float4*>(table + k * 8 + s0);

    // Per-row bias (broadcast over v,s).
    float bm[WINSZ];
#pragma unroll
    for (int m = 0; m < WINSZ; m++)
        bm[m] = bias[m];

    // Front-batched x loads: MLP = 8, each warp-coalesced to a 128B line.
    float4 xv[WINSZ];
#pragma unroll
    for (int n = 0; n < WINSZ; n++)
        xv[n] = xin[n * ROWF4];

#pragma unroll
    for (int m = 0; m < WINSZ; m++) {
        float4 acc = make_float4(bm[m], bm[m], bm[m], bm[m]);
#pragma unroll
        for (int n = 0; n < WINSZ; n++) {
            const float4 w = wt[m - n + 7];
            acc.x = fmaf(w.x, xv[n].x, acc.x);
            acc.y = fmaf(w.y, xv[n].y, acc.y);
            acc.z = fmaf(w.z, xv[n].z, acc.z);
            acc.w = fmaf(w.w, xv[n].w, acc.w);
        }
        o[m * ROWF4] = acc;
    }
}

extern "C" void kernel_launch(void* const* d_in, const int* in_sizes, int n_in,
                              void* d_out, int out_size) {
    const float* x     = (const float*)d_in[0];   // (B, NWIN, WIN, DIM)
    const float* table = (const float*)d_in[1];   // (15, 8)
    const float* bias  = (const float*)d_in[2];   // (1, 8, 1)
    float* out = (float*)d_out;

    const int n_win = in_sizes[0] / (WINSZ * DIMSZ);   // B * NWIN = 25088
    const int total_threads = n_win * VEC;             // 2,408,448
    const int block = 256;
    const int grid  = (total_threads + block - 1) / block;

    lpm_kernel<<<grid, block>>>(x, table, bias, out, n_win);
}